// round 17
// baseline (speedup 1.0000x reference)
#include <cuda_runtime.h>
#include <cstdint>

#define DIM 256
#define OUT 8
#define CHUNK 32          // dims per pipeline chunk
#define NCHUNK 8          // DIM / CHUNK
#define ROWF 32           // floats per row (XOR piece swizzle handles banks)
#define TPG 64            // tokens per warp group (2 per lane)
#define WARPS 4           // warps per block (128 threads)
#define STAGES 3

#define STAGE_FLOATS (TPG * ROWF)                     // 2048 (8KB)
#define XBUF_FLOATS  (WARPS * STAGES * STAGE_FLOATS)  // 24576
#define XBUF_BYTES   (XBUF_FLOATS * 4)                // 98304
#define WP_BYTES     (DIM / 2 * OUT * 8)              // 8192
#define SMEM_TOTAL   (XBUF_BYTES + WP_BYTES + 96 * 4) // ~106.9KB -> 2 blocks/SM

__device__ __forceinline__ unsigned long long pk2(float lo, float hi) {
    unsigned long long r;
    asm("mov.b64 %0, {%1,%2};" : "=l"(r) : "f"(lo), "f"(hi));
    return r;
}
__device__ __forceinline__ unsigned long long fma2(unsigned long long a, unsigned long long b,
                                                   unsigned long long c) {
    unsigned long long d;
    asm("fma.rn.f32x2 %0, %1, %2, %3;" : "=l"(d) : "l"(a), "l"(b), "l"(c));
    return d;
}
__device__ __forceinline__ void cp16_ef(uint32_t saddr, const float* gptr, unsigned long long pol) {
    asm volatile("cp.async.cg.shared.global.L2::cache_hint [%0], [%1], 16, %2;"
                 :: "r"(saddr), "l"(gptr), "l"(pol));
}

struct EpiParams { const float *W2, *b1, *b2, *g, *bt; };

__device__ __forceinline__ void epilogue(const unsigned long long* acc, const EpiParams& ep,
                                         float* __restrict__ out, int tok)
{
    float gg[OUT];
    #pragma unroll
    for (int o = 0; o < OUT; o++) {
        float2 p = *(const float2*)&acc[o];
        float hv = p.x + p.y + ep.b1[o];
        gg[o] = 0.5f * hv * (1.0f + erff(hv * 0.70710678118654752440f));
    }
    float y[OUT];
    #pragma unroll
    for (int p = 0; p < OUT; p++) {
        float s = ep.b2[p];
        #pragma unroll
        for (int o = 0; o < OUT; o++) s = fmaf(ep.W2[p * 8 + o], gg[o], s);
        y[p] = s;
    }
    float mu = 0.0f;
    #pragma unroll
    for (int p = 0; p < OUT; p++) mu += y[p];
    mu *= 0.125f;
    float var = 0.0f;
    #pragma unroll
    for (int p = 0; p < OUT; p++) { float d = y[p] - mu; var = fmaf(d, d, var); }
    var *= 0.125f;
    float rs = rsqrtf(var + 1e-5f);

    float4 o0, o1;
    o0.x = (y[0] - mu) * rs * ep.g[0] + ep.bt[0];
    o0.y = (y[1] - mu) * rs * ep.g[1] + ep.bt[1];
    o0.z = (y[2] - mu) * rs * ep.g[2] + ep.bt[2];
    o0.w = (y[3] - mu) * rs * ep.g[3] + ep.bt[3];
    o1.x = (y[4] - mu) * rs * ep.g[4] + ep.bt[4];
    o1.y = (y[5] - mu) * rs * ep.g[5] + ep.bt[5];
    o1.z = (y[6] - mu) * rs * ep.g[6] + ep.bt[6];
    o1.w = (y[7] - mu) * rs * ep.g[7] + ep.bt[7];
    float* op = out + (size_t)tok * 8;
    asm volatile("st.global.cs.v4.f32 [%0], {%1,%2,%3,%4};"
                 :: "l"(op), "f"(o0.x), "f"(o0.y), "f"(o0.z), "f"(o0.w));
    asm volatile("st.global.cs.v4.f32 [%0], {%1,%2,%3,%4};"
                 :: "l"(op + 4), "f"(o1.x), "f"(o1.y), "f"(o1.z), "f"(o1.w));
}

__global__ __launch_bounds__(128, 2)
void ffn_kernel(const float* __restrict__ x, const float* __restrict__ W1,
                const float* __restrict__ b1, const float* __restrict__ W2,
                const float* __restrict__ b2, const float* __restrict__ gamma,
                const float* __restrict__ beta, float* __restrict__ out, int ntok)
{
    extern __shared__ char smem_raw[];
    float* xbuf = (float*)smem_raw;
    unsigned long long* Wp = (unsigned long long*)(smem_raw + XBUF_BYTES);
    float* tail = (float*)(smem_raw + XBUF_BYTES + WP_BYTES);
    float* sW2 = tail;          // 64
    float* sb1 = tail + 64;     // 8
    float* sb2 = tail + 72;     // 8
    float* sg  = tail + 80;     // 8
    float* sbt = tail + 88;     // 8

    const int tid = threadIdx.x;

    // ---- one-time init: packed W1 dim-pairs Wp[dp*8+o] = {W1[o][2dp], W1[o][2dp+1]} ----
    {
        int e = tid * 8;                // 128 threads x 8 = 1024 entries
        #pragma unroll
        for (int q = 0; q < 8; q++) {
            int idx = e + q;
            int d = idx >> 3;
            int o = idx & 7;
            Wp[idx] = pk2(W1[o * DIM + 2 * d], W1[o * DIM + 2 * d + 1]);
        }
        if (tid < 64) sW2[tid] = W2[tid];
        if (tid < 8) { sb1[tid] = b1[tid]; sb2[tid] = b2[tid]; sg[tid] = gamma[tid]; sbt[tid] = beta[tid]; }
    }
    __syncthreads();

    const int lane = tid & 31;
    const int warp = tid >> 5;
    const int warp_global = blockIdx.x * WARPS + warp;
    const long long nwarps = (long long)gridDim.x * WARPS;
    const int ngroups = (ntok + TPG - 1) / TPG;

    // balanced contiguous group range for this warp
    const int g0 = (int)((long long)warp_global * ngroups / nwarps);
    const int g1 = (int)((long long)(warp_global + 1) * ngroups / nwarps);
    const int N = (g1 - g0) * NCHUNK;           // flattened chunk count

    float* wtile = xbuf + warp * STAGES * STAGE_FLOATS;
    const uint32_t wtile_su = (uint32_t)__cvta_generic_to_shared(wtile);
    EpiParams ep{sW2, sb1, sb2, sg, sbt};

    // L2 evict_first policy for the use-once x stream
    unsigned long long pol;
    asm("createpolicy.fractional.L2::evict_first.b64 %0, 1.0;" : "=l"(pol));

    // staging: 64 rows x 8 pieces of 16B per stage; lane covers rows it*4+(lane>>3),
    // piece j0 = lane&7 at physical piece j0^(r&7) (conflict-free write + read)
    const int r0 = lane >> 3, j0 = lane & 7;
    const ulonglong2* Wp2 = (const ulonglong2*)Wp;
    const float* rowA = wtile + lane * ROWF;
    const float* rowB = rowA + 32 * ROWF;
    const int lA = lane & 7;

    // ---- prefetch flattened chunk k into stage stg ----
    auto prefetch = [&](int k, int stg) {
        const int base = (g0 + (k >> 3)) * TPG;
        const int c = k & 7;
        const float* xg = x + (size_t)base * DIM + c * CHUNK;
        const uint32_t sbase = wtile_su + (uint32_t)(stg * STAGE_FLOATS) * 4;
        if (base + TPG <= ntok) {
            #pragma unroll
            for (int it = 0; it < 16; it++) {
                int r = it * 4 + r0;
                int pj = j0 ^ (r & 7);
                cp16_ef(sbase + (uint32_t)(r * ROWF + pj * 4) * 4,
                        xg + (size_t)r * DIM + j0 * 4, pol);
            }
        } else {
            #pragma unroll
            for (int it = 0; it < 16; it++) {
                int r = it * 4 + r0;
                int pj = j0 ^ (r & 7);
                if (base + r < ntok)
                    cp16_ef(sbase + (uint32_t)(r * ROWF + pj * 4) * 4,
                            xg + (size_t)r * DIM + j0 * 4, pol);
            }
        }
        asm volatile("cp.async.commit_group;");
    };

    unsigned long long accA[OUT], accB[OUT];
    #pragma unroll
    for (int o = 0; o < OUT; o++) { accA[o] = 0ull; accB[o] = 0ull; }

    if (N > 0) prefetch(0, 0);
    if (N > 1) prefetch(1, 1);

    int stp = 2;    // stage of next prefetch (k+2)
    int stc = 0;    // stage of current compute (k)

    for (int k = 0; k < N; k++) {
        if (k + 2 < N) {
            prefetch(k + 2, stp);
            stp = (stp == 2) ? 0 : stp + 1;
            asm volatile("cp.async.wait_group 2;");
        } else if (k + 1 < N) {
            asm volatile("cp.async.wait_group 1;");
        } else {
            asm volatile("cp.async.wait_group 0;");
        }
        __syncwarp();

        // ---- compute chunk (k&7) from stage stc: 2 tokens per thread ----
        {
            const int c = k & 7;
            const float* rA = rowA + stc * STAGE_FLOATS;
            const float* rB = rowB + stc * STAGE_FLOATS;
            #pragma unroll
            for (int i = 0; i < 8; i++) {
                ulonglong2 xa = *(const ulonglong2*)(rA + ((i ^ lA) << 2));
                ulonglong2 xb = *(const ulonglong2*)(rB + ((i ^ lA) << 2));
                const ulonglong2* w = Wp2 + (size_t)(c * 16 + 2 * i) * 4;
                {
                    ulonglong2 w0 = w[0];
                    accA[0] = fma2(xa.x, w0.x, accA[0]);  accB[0] = fma2(xb.x, w0.x, accB[0]);
                    accA[1] = fma2(xa.x, w0.y, accA[1]);  accB[1] = fma2(xb.x, w0.y, accB[1]);
                    ulonglong2 w1 = w[1];
                    accA[2] = fma2(xa.x, w1.x, accA[2]);  accB[2] = fma2(xb.x, w1.x, accB[2]);
                    accA[3] = fma2(xa.x, w1.y, accA[3]);  accB[3] = fma2(xb.x, w1.y, accB[3]);
                    ulonglong2 w2 = w[2];
                    accA[4] = fma2(xa.x, w2.x, accA[4]);  accB[4] = fma2(xb.x, w2.x, accB[4]);
                    accA[5] = fma2(xa.x, w2.y, accA[5]);  accB[5] = fma2(xb.x, w2.y, accB[5]);
                    ulonglong2 w3 = w[3];
                    accA[6] = fma2(xa.x, w3.x, accA[6]);  accB[6] = fma2(xb.x, w3.x, accB[6]);
                    accA[7] = fma2(xa.x, w3.y, accA[7]);  accB[7] = fma2(xb.x, w3.y, accB[7]);
                }
                {
                    ulonglong2 w4 = w[4];
                    accA[0] = fma2(xa.y, w4.x, accA[0]);  accB[0] = fma2(xb.y, w4.x, accB[0]);
                    accA[1] = fma2(xa.y, w4.y, accA[1]);  accB[1] = fma2(xb.y, w4.y, accB[1]);
                    ulonglong2 w5 = w[5];
                    accA[2] = fma2(xa.y, w5.x, accA[2]);  accB[2] = fma2(xb.y, w5.x, accB[2]);
                    accA[3] = fma2(xa.y, w5.y, accA[3]);  accB[3] = fma2(xb.y, w5.y, accB[3]);
                    ulonglong2 w6 = w[6];
                    accA[4] = fma2(xa.y, w6.x, accA[4]);  accB[4] = fma2(xb.y, w6.x, accB[4]);
                    accA[5] = fma2(xa.y, w6.y, accA[5]);  accB[5] = fma2(xb.y, w6.y, accB[5]);
                    ulonglong2 w7 = w[7];
                    accA[6] = fma2(xa.y, w7.x, accA[6]);  accB[6] = fma2(xb.y, w7.x, accB[6]);
                    accA[7] = fma2(xa.y, w7.y, accA[7]);  accB[7] = fma2(xb.y, w7.y, accB[7]);
                }
            }
            stc = (stc == 2) ? 0 : stc + 1;
        }
        __syncwarp();

        // ---- group boundary: epilogue + accumulator reset ----
        if ((k & 7) == 7) {
            const int base = (g0 + (k >> 3)) * TPG;
            const int tokA = base + lane;
            const int tokB = base + 32 + lane;
            if (tokA < ntok) epilogue(accA, ep, out, tokA);
            if (tokB < ntok) epilogue(accB, ep, out, tokB);
            #pragma unroll
            for (int o = 0; o < OUT; o++) { accA[o] = 0ull; accB[o] = 0ull; }
        }
    }
}

extern "C" void kernel_launch(void* const* d_in, const int* in_sizes, int n_in,
                              void* d_out, int out_size)
{
    const float* x     = (const float*)d_in[0];
    const float* W1    = (const float*)d_in[1];
    const float* b1    = (const float*)d_in[2];
    const float* W2    = (const float*)d_in[3];
    const float* b2    = (const float*)d_in[4];
    const float* gamma = (const float*)d_in[5];
    const float* beta  = (const float*)d_in[6];
    float* out = (float*)d_out;

    int ntok = in_sizes[0] / DIM;               // 262144 for the bench shape
    int ngroups = (ntok + TPG - 1) / TPG;       // warp-groups of 64 tokens

    int blocks = 296;                            // persistent: 2 blocks/SM
    int maxb = (ngroups + WARPS - 1) / WARPS;
    if (blocks > maxb) blocks = maxb;
    if (blocks < 1) blocks = 1;

    cudaFuncSetAttribute(ffn_kernel, cudaFuncAttributeMaxDynamicSharedMemorySize, SMEM_TOTAL);
    ffn_kernel<<<blocks, 128, SMEM_TOTAL>>>(x, W1, b1, W2, b2, gamma, beta, out, ntok);
}